// round 1
// baseline (speedup 1.0000x reference)
#include <cuda_runtime.h>
#include <cuda_bf16.h>
#include <math.h>

// Problem constants
#define BATCH 4
#define NN 4096
#define DD 256
#define PP 64
#define ALPHA 0.2f
#define KCAP 255

// Scratch for per-batch setup results (no cudaMalloc allowed)
__device__ float g_v[BATCH][DD];      // Wk @ q / sqrt(64)
__device__ float g_theta[BATCH];

// ---------------------------------------------------------------------------
// Kernel A: per-batch setup. grid=BATCH, block=256.
//  - seed_idx = argmax(cluster_mask[b])  (first index of max; mask is 0/1)
//  - q = x[b, seed] @ Wq                 [64]
//  - v = (Wk @ q) / 8                    [256]
//  - theta = MLP(concat(seed_ctx, local_stats))
// ---------------------------------------------------------------------------
__global__ void setup_kernel(const float* __restrict__ x,
                             const float* __restrict__ cmask,
                             const float* __restrict__ seed_ctx,
                             const float* __restrict__ local_stats,
                             const float* __restrict__ Wq,
                             const float* __restrict__ Wk,
                             const float* __restrict__ w1,
                             const float* __restrict__ b1,
                             const float* __restrict__ w2,
                             const float* __restrict__ b2)
{
    __shared__ int s_seed;
    __shared__ float s_q[PP];
    __shared__ float s_h[128];

    const int b = blockIdx.x;
    const int tid = threadIdx.x;

    if (tid == 0) s_seed = NN;   // sentinel
    __syncthreads();

    // first index with mask set (strided scan, keep first hit per thread)
    int local = NN;
    for (int n = tid; n < NN; n += 256) {
        if (cmask[b * NN + n] > 0.5f) { local = n; break; }
    }
    if (local < NN) atomicMin(&s_seed, local);
    __syncthreads();
    const int seed = (s_seed < NN) ? s_seed : 0;

    // q[p] = sum_d x[b,seed,d] * Wq[d,p]
    if (tid < PP) {
        const float* xr = x + ((size_t)b * NN + seed) * DD;
        float acc = 0.f;
        #pragma unroll 4
        for (int d = 0; d < DD; d++) acc += xr[d] * Wq[d * PP + tid];
        s_q[tid] = acc;
    }
    __syncthreads();

    // v[d] = (sum_p Wk[d,p]*q[p]) / sqrt(64)
    if (tid < DD) {
        float acc = 0.f;
        #pragma unroll 8
        for (int p = 0; p < PP; p++) acc += Wk[tid * PP + p] * s_q[p];
        g_v[b][tid] = acc * 0.125f;
    }

    // theta head: h = relu([seed_ctx|local_stats] @ w1 + b1); theta = h@w2 + b2
    if (tid < 128) {
        float acc = b1[tid];
        const float* sc = seed_ctx + (size_t)b * 384;
        const float* ls = local_stats + (size_t)b * 128;
        for (int i = 0; i < 384; i++)  acc += sc[i] * w1[i * 128 + tid];
        for (int i = 0; i < 128; i++)  acc += ls[i] * w1[(384 + i) * 128 + tid];
        s_h[tid] = fmaxf(acc, 0.f);
    }
    __syncthreads();
    if (tid == 0) {
        float th = b2[0];
        for (int j = 0; j < 128; j++) th += s_h[j] * w2[j];
        g_theta[b] = th;
    }
}

// ---------------------------------------------------------------------------
// Kernel B: the streaming kernel. One warp per adjacency row.
// grid = BATCH * 512 blocks, 256 threads (8 warps -> 8 rows / block).
// Per row: e2c = adj_row . cmask, deg = sum(adj_row), score = x_row . v.
// cmask cached in shared per block (keeps L2 traffic at ~32 MB, not 268 MB).
// ---------------------------------------------------------------------------
__global__ void __launch_bounds__(256) main_kernel(
        const float* __restrict__ x,
        const float* __restrict__ adj,
        const float* __restrict__ cmask,
        const float* __restrict__ candmask,
        float* __restrict__ out_p)
{
    __shared__ float s_cm[NN];
    __shared__ float s_v[DD];
    __shared__ float s_th;

    const int b   = blockIdx.x >> 9;          // 512 blocks per batch
    const int blk = blockIdx.x & 511;
    const int tid = threadIdx.x;

    // stage cluster_mask (16 KB) + v (1 KB) + theta into shared
    {
        const float4* cm4 = (const float4*)(cmask + (size_t)b * NN);
        float4* s4 = (float4*)s_cm;
        #pragma unroll
        for (int i = tid; i < NN / 4; i += 256) s4[i] = cm4[i];
        if (tid < DD) s_v[tid] = g_v[b][tid];
        if (tid == 0) s_th = g_theta[b];
    }
    __syncthreads();

    const int w    = tid >> 5;
    const int lane = tid & 31;
    const int n    = (blk << 3) + w;

    const float4* a4 = (const float4*)(adj + ((size_t)b * NN + n) * NN);
    const float4* c4 = (const float4*)s_cm;

    float e2c = 0.f, deg = 0.f;
    #pragma unroll 4
    for (int i = lane; i < NN / 4; i += 32) {
        float4 a = a4[i];
        float4 c = c4[i];
        deg += (a.x + a.y) + (a.z + a.w);
        e2c += a.x * c.x + a.y * c.y + a.z * c.z + a.w * c.w;
    }

    float sc = 0.f;
    const float4* x4 = (const float4*)(x + ((size_t)b * NN + n) * DD);
    const float4* v4 = (const float4*)s_v;
    #pragma unroll
    for (int i = lane; i < DD / 4; i += 32) {
        float4 xv = x4[i];
        float4 vv = v4[i];
        sc += xv.x * vv.x + xv.y * vv.y + xv.z * vv.z + xv.w * vv.w;
    }

    // warp tree-reduce the three accumulators
    #pragma unroll
    for (int o = 16; o > 0; o >>= 1) {
        e2c += __shfl_xor_sync(0xffffffffu, e2c, o);
        deg += __shfl_xor_sync(0xffffffffu, deg, o);
        sc  += __shfl_xor_sync(0xffffffffu, sc,  o);
    }

    if (lane == 0) {
        deg = fmaxf(deg, 1.0f);
        float logit = sc + ALPHA * (e2c / deg) - s_th;   // TAU = 1
        float p = 1.0f / (1.0f + expf(-logit));
        p *= candmask[(size_t)b * NN + n];
        out_p[(size_t)b * NN + n] = p;
    }
}

// ---------------------------------------------------------------------------
// Kernel C: per-batch finalize. grid=BATCH, block=1024.
// Count p>0.5; if >255 do exact jax-semantics top-255 (ties -> lower index)
// via bitonic sort of 64-bit keys in shared; write hard, trimmed p, and stats.
// Output layout: [hard(16384) | p(16384) | theta(4) | expected(4) | mean(4)]
// ---------------------------------------------------------------------------
__global__ void __launch_bounds__(1024) finalize_kernel(float* __restrict__ out)
{
    __shared__ unsigned long long s_key[NN];   // 32 KB
    __shared__ int s_cnt;
    __shared__ float s_sum;
    __shared__ unsigned long long s_kth;

    const int b = blockIdx.x;
    const int tid = threadIdx.x;
    float* out_hard = out;
    float* out_p    = out + BATCH * NN;

    if (tid == 0) { s_cnt = 0; s_sum = 0.f; }
    __syncthreads();

    int cnt = 0;
    for (int i = tid; i < NN; i += 1024) {
        float p = out_p[(size_t)b * NN + i];
        s_key[i] = ((unsigned long long)__float_as_uint(p) << 32)
                 | (unsigned int)(~i);
        cnt += (p > 0.5f) ? 1 : 0;
    }
    #pragma unroll
    for (int o = 16; o > 0; o >>= 1) cnt += __shfl_xor_sync(0xffffffffu, cnt, o);
    if ((tid & 31) == 0) atomicAdd(&s_cnt, cnt);
    __syncthreads();

    const bool trim = (s_cnt > KCAP);
    if (trim) {
        // bitonic sort descending (key = (p_bits, ~idx) -> jax tie order)
        for (unsigned k = 2; k <= NN; k <<= 1) {
            for (unsigned j = k >> 1; j > 0; j >>= 1) {
                for (unsigned i = tid; i < NN; i += 1024) {
                    unsigned ixj = i ^ j;
                    if (ixj > i) {
                        unsigned long long a = s_key[i];
                        unsigned long long c = s_key[ixj];
                        bool up = ((i & k) == 0);
                        if (up == (a < c)) { s_key[i] = c; s_key[ixj] = a; }
                    }
                }
                __syncthreads();
            }
        }
        if (tid == 0) s_kth = s_key[KCAP - 1];   // 255th largest (0-based 254)
        __syncthreads();
    }
    const unsigned long long kth = trim ? s_kth : 0ULL;

    float lsum = 0.f;
    for (int i = tid; i < NN; i += 1024) {
        float p = out_p[(size_t)b * NN + i];
        unsigned long long key = ((unsigned long long)__float_as_uint(p) << 32)
                               | (unsigned int)(~i);
        if (trim && key < kth) p = 0.f;
        out_p[(size_t)b * NN + i]    = p;
        out_hard[(size_t)b * NN + i] = (p > 0.5f) ? 1.0f : 0.0f;
        lsum += p;
    }
    #pragma unroll
    for (int o = 16; o > 0; o >>= 1) lsum += __shfl_xor_sync(0xffffffffu, lsum, o);
    if ((tid & 31) == 0) atomicAdd(&s_sum, lsum);
    __syncthreads();

    if (tid == 0) {
        float* tail = out + 2 * BATCH * NN;
        tail[b]             = g_theta[b];                 // theta
        tail[BATCH + b]     = s_sum;                      // expected_size
        tail[2 * BATCH + b] = s_sum * (1.0f / (float)NN); // mean_p
    }
}

// ---------------------------------------------------------------------------
extern "C" void kernel_launch(void* const* d_in, const int* in_sizes, int n_in,
                              void* d_out, int out_size)
{
    const float* x           = (const float*)d_in[0];
    const float* adj         = (const float*)d_in[1];
    const float* seed_ctx    = (const float*)d_in[2];
    const float* local_stats = (const float*)d_in[3];
    const float* cmask       = (const float*)d_in[4];
    const float* candmask    = (const float*)d_in[5];
    const float* Wq          = (const float*)d_in[6];
    const float* Wk          = (const float*)d_in[7];
    const float* w1          = (const float*)d_in[8];
    const float* b1          = (const float*)d_in[9];
    const float* w2          = (const float*)d_in[10];
    const float* b2          = (const float*)d_in[11];
    float* out = (float*)d_out;

    setup_kernel<<<BATCH, 256>>>(x, cmask, seed_ctx, local_stats,
                                 Wq, Wk, w1, b1, w2, b2);
    main_kernel<<<BATCH * 512, 256>>>(x, adj, cmask, candmask,
                                      out + BATCH * NN);
    finalize_kernel<<<BATCH, 1024>>>(out);
}

// round 3
// speedup vs baseline: 2.0682x; 2.0682x over previous
#include <cuda_runtime.h>
#include <cuda_bf16.h>
#include <math.h>

// Problem constants
#define BATCH 4
#define NN 4096
#define DD 256
#define PP 64
#define ALPHA 0.2f
#define KCAP 255

// Scratch for per-batch setup results (no cudaMalloc allowed)
__device__ float g_v[BATCH][DD];      // Wk @ q / sqrt(64)
__device__ float g_theta[BATCH];

// ---------------------------------------------------------------------------
// Kernel A: per-batch setup. grid=BATCH, block=1024. Fully parallel phases,
// no serial dependent-load chains, no single-thread loops.
// ---------------------------------------------------------------------------
__global__ void __launch_bounds__(1024) setup_kernel(
        const float* __restrict__ x,
        const float* __restrict__ cmask,
        const float* __restrict__ seed_ctx,
        const float* __restrict__ local_stats,
        const float* __restrict__ Wq,
        const float* __restrict__ Wk,
        const float* __restrict__ w1,
        const float* __restrict__ b1,
        const float* __restrict__ w2,
        const float* __restrict__ b2)
{
    __shared__ int   s_seed;
    __shared__ __align__(16) float s_x[DD];           // x[b, seed, :]
    __shared__ __align__(16) float s_in[512];         // theta_in
    __shared__ __align__(16) float s_q[PP];
    __shared__ __align__(16) float s_qpart[16][PP];   // 4 KB
    __shared__ __align__(16) float s_hpart[8][128];   // 4 KB
    __shared__ __align__(16) float s_h[128];

    const int b = blockIdx.x;
    const int t = threadIdx.x;
    const int lane = t & 31;

    if (t == 0) s_seed = NN;
    __syncthreads();

    // ---- seed = first index with cmask > 0.5 (parallel, branch-free) ----
    {
        int lm = NN;
        #pragma unroll
        for (int j = 3; j >= 0; j--) {          // descending so smallest wins
            int i = j * 1024 + t;
            if (cmask[(size_t)b * NN + i] > 0.5f) lm = i;
        }
        #pragma unroll
        for (int o = 16; o > 0; o >>= 1)
            lm = min(lm, __shfl_xor_sync(0xffffffffu, lm, o));
        if (lane == 0 && lm < NN) atomicMin(&s_seed, lm);
    }
    __syncthreads();
    const int seed = (s_seed < NN) ? s_seed : 0;

    // ---- stage x_seed row and theta_in ----
    if (t < DD)  s_x[t]  = x[((size_t)b * NN + seed) * DD + t];
    if (t < 384) s_in[t] = seed_ctx[(size_t)b * 384 + t];
    else if (t < 512) s_in[t] = local_stats[(size_t)b * 128 + (t - 384)];
    __syncthreads();

    // ---- q[p] = sum_d x_seed[d] * Wq[d,p]   (64 outputs x 16 chunks) ----
    {
        const int p = t & 63;
        const int c = t >> 6;                   // 0..15, 16 d's each
        float acc = 0.f;
        #pragma unroll
        for (int dd = 0; dd < 16; dd++) {
            int d = c * 16 + dd;
            acc += s_x[d] * Wq[d * PP + p];
        }
        s_qpart[c][p] = acc;
    }
    __syncthreads();
    if (t < PP) {
        float a = 0.f;
        #pragma unroll
        for (int c = 0; c < 16; c++) a += s_qpart[c][t];
        s_q[t] = a;
    }
    __syncthreads();

    // ---- v[d] = (Wk[d,:] . q) / 8   (256 outputs x 4 threads) ----
    {
        const int d = t >> 2;
        const int j = t & 3;
        const float4* wk4 = (const float4*)(Wk + d * PP + j * 16);
        const float4* q4  = (const float4*)(s_q + j * 16);
        float a = 0.f;
        #pragma unroll
        for (int k = 0; k < 4; k++) {
            float4 wv = wk4[k];
            float4 qv = q4[k];
            a += wv.x * qv.x + wv.y * qv.y + wv.z * qv.z + wv.w * qv.w;
        }
        a += __shfl_xor_sync(0xffffffffu, a, 1);
        a += __shfl_xor_sync(0xffffffffu, a, 2);
        if (j == 0) g_v[b][d] = a * 0.125f;
    }

    // ---- theta head: h = relu(theta_in @ w1 + b1) (128 x 8 chunks) ----
    {
        const int h = t & 127;
        const int c = t >> 7;                   // 0..7, 64 inputs each
        float a = 0.f;
        #pragma unroll 8
        for (int ii = 0; ii < 64; ii++) {
            int i = c * 64 + ii;
            a += s_in[i] * w1[i * 128 + h];     // coalesced across h
        }
        s_hpart[c][h] = a;
    }
    __syncthreads();
    if (t < 128) {
        float a = b1[t];
        #pragma unroll
        for (int c = 0; c < 8; c++) a += s_hpart[c][t];
        s_h[t] = fmaxf(a, 0.f);
    }
    __syncthreads();
    if (t < 32) {
        float a = 0.f;
        #pragma unroll
        for (int j = 0; j < 4; j++) a += s_h[t + 32 * j] * w2[t + 32 * j];
        #pragma unroll
        for (int o = 16; o > 0; o >>= 1) a += __shfl_xor_sync(0xffffffffu, a, o);
        if (t == 0) g_theta[b] = a + b2[0];
    }
}

// ---------------------------------------------------------------------------
// Kernel B: streaming kernel. One warp per adjacency row.
// grid = BATCH * 512 blocks, 256 threads (8 warps -> 8 rows / block).
// ---------------------------------------------------------------------------
__global__ void __launch_bounds__(256) main_kernel(
        const float* __restrict__ x,
        const float* __restrict__ adj,
        const float* __restrict__ cmask,
        const float* __restrict__ candmask,
        float* __restrict__ out_p)
{
    __shared__ __align__(16) float s_cm[NN];
    __shared__ __align__(16) float s_v[DD];
    __shared__ float s_th;

    const int b   = blockIdx.x >> 9;
    const int blk = blockIdx.x & 511;
    const int tid = threadIdx.x;

    {
        const float4* cm4 = (const float4*)(cmask + (size_t)b * NN);
        float4* s4 = (float4*)s_cm;
        #pragma unroll
        for (int i = tid; i < NN / 4; i += 256) s4[i] = cm4[i];
        if (tid < DD) s_v[tid] = g_v[b][tid];
        if (tid == 0) s_th = g_theta[b];
    }
    __syncthreads();

    const int w    = tid >> 5;
    const int lane = tid & 31;
    const int n    = (blk << 3) + w;

    const float4* a4 = (const float4*)(adj + ((size_t)b * NN + n) * NN);
    const float4* c4 = (const float4*)s_cm;

    float e2c = 0.f, deg = 0.f;
    #pragma unroll 8
    for (int i = lane; i < NN / 4; i += 32) {
        float4 a = a4[i];
        float4 c = c4[i];
        deg += (a.x + a.y) + (a.z + a.w);
        e2c += a.x * c.x + a.y * c.y + a.z * c.z + a.w * c.w;
    }

    float sc = 0.f;
    const float4* x4 = (const float4*)(x + ((size_t)b * NN + n) * DD);
    const float4* v4 = (const float4*)s_v;
    #pragma unroll
    for (int i = lane; i < DD / 4; i += 32) {
        float4 xv = x4[i];
        float4 vv = v4[i];
        sc += xv.x * vv.x + xv.y * vv.y + xv.z * vv.z + xv.w * vv.w;
    }

    #pragma unroll
    for (int o = 16; o > 0; o >>= 1) {
        e2c += __shfl_xor_sync(0xffffffffu, e2c, o);
        deg += __shfl_xor_sync(0xffffffffu, deg, o);
        sc  += __shfl_xor_sync(0xffffffffu, sc,  o);
    }

    if (lane == 0) {
        deg = fmaxf(deg, 1.0f);
        float logit = sc + ALPHA * (e2c / deg) - s_th;   // TAU = 1
        float p = 1.0f / (1.0f + expf(-logit));
        p *= candmask[(size_t)b * NN + n];
        out_p[(size_t)b * NN + n] = p;
    }
}

// ---------------------------------------------------------------------------
// Kernel C: per-batch finalize with 64-bit radix select (exact jax top-k
// semantics: key = (p_bits << 32) | ~idx, unique keys, ties -> lower index).
// Output layout: [hard(16384) | p(16384) | theta(4) | expected(4) | mean(4)]
// ---------------------------------------------------------------------------
__global__ void __launch_bounds__(1024) finalize_kernel(float* __restrict__ out)
{
    __shared__ unsigned long long s_key[NN];   // 32 KB
    __shared__ int s_hist[256];
    __shared__ int s_cnt;
    __shared__ float s_sum;
    __shared__ unsigned long long s_prefix;
    __shared__ int s_k;

    const int b = blockIdx.x;
    const int t = threadIdx.x;
    float* out_hard = out;
    float* out_p    = out + BATCH * NN;

    if (t == 0) { s_cnt = 0; s_sum = 0.f; s_prefix = 0ULL; s_k = KCAP; }
    __syncthreads();

    int cnt = 0;
    #pragma unroll
    for (int j = 0; j < 4; j++) {
        int i = j * 1024 + t;
        float p = out_p[(size_t)b * NN + i];
        s_key[i] = ((unsigned long long)__float_as_uint(p) << 32)
                 | (unsigned int)(~i);
        cnt += (p > 0.5f) ? 1 : 0;
    }
    #pragma unroll
    for (int o = 16; o > 0; o >>= 1) cnt += __shfl_xor_sync(0xffffffffu, cnt, o);
    if ((t & 31) == 0) atomicAdd(&s_cnt, cnt);
    __syncthreads();

    const bool trim = (s_cnt > KCAP);
    if (trim) {
        // 8 rounds of 8-bit radix select, MSB first, over unique 64-bit keys.
        for (int round = 0; round < 8; round++) {
            const int shift = 56 - 8 * round;
            if (t < 256) s_hist[t] = 0;
            __syncthreads();
            const unsigned long long prefix = s_prefix;
            // high bits above current byte must match prefix
            const int hshift = shift + 8;
            #pragma unroll
            for (int j = 0; j < 4; j++) {
                unsigned long long key = s_key[j * 1024 + t];
                bool match = (round == 0) ||
                             ((key >> hshift) == (prefix >> hshift));
                if (match) {
                    int byte = (int)((key >> shift) & 255ULL);
                    atomicAdd(&s_hist[byte], 1);
                }
            }
            __syncthreads();
            if (t == 0) {
                int k = s_k, cum = 0, bin = 0;
                for (int byte = 255; byte >= 0; byte--) {
                    cum += s_hist[byte];
                    if (cum >= k) { bin = byte; k -= (cum - s_hist[byte]); break; }
                }
                s_k = k;
                s_prefix = prefix | ((unsigned long long)bin << shift);
            }
            __syncthreads();
        }
    }
    const unsigned long long kth = trim ? s_prefix : 0ULL;

    float lsum = 0.f;
    #pragma unroll
    for (int j = 0; j < 4; j++) {
        int i = j * 1024 + t;
        unsigned long long key = s_key[i];
        float p = __uint_as_float((unsigned int)(key >> 32));
        if (trim && key < kth) p = 0.f;
        out_p[(size_t)b * NN + i]    = p;
        out_hard[(size_t)b * NN + i] = (p > 0.5f) ? 1.0f : 0.0f;
        lsum += p;
    }
    #pragma unroll
    for (int o = 16; o > 0; o >>= 1) lsum += __shfl_xor_sync(0xffffffffu, lsum, o);
    if ((t & 31) == 0) atomicAdd(&s_sum, lsum);
    __syncthreads();

    if (t == 0) {
        float* tail = out + 2 * BATCH * NN;
        tail[b]             = g_theta[b];                 // theta
        tail[BATCH + b]     = s_sum;                      // expected_size
        tail[2 * BATCH + b] = s_sum * (1.0f / (float)NN); // mean_p
    }
}

// ---------------------------------------------------------------------------
extern "C" void kernel_launch(void* const* d_in, const int* in_sizes, int n_in,
                              void* d_out, int out_size)
{
    const float* x           = (const float*)d_in[0];
    const float* adj         = (const float*)d_in[1];
    const float* seed_ctx    = (const float*)d_in[2];
    const float* local_stats = (const float*)d_in[3];
    const float* cmask       = (const float*)d_in[4];
    const float* candmask    = (const float*)d_in[5];
    const float* Wq          = (const float*)d_in[6];
    const float* Wk          = (const float*)d_in[7];
    const float* w1          = (const float*)d_in[8];
    const float* b1          = (const float*)d_in[9];
    const float* w2          = (const float*)d_in[10];
    const float* b2          = (const float*)d_in[11];
    float* out = (float*)d_out;

    setup_kernel<<<BATCH, 1024>>>(x, cmask, seed_ctx, local_stats,
                                  Wq, Wk, w1, b1, w2, b2);
    main_kernel<<<BATCH * 512, 256>>>(x, adj, cmask, candmask,
                                      out + BATCH * NN);
    finalize_kernel<<<BATCH, 1024>>>(out);
}